// round 5
// baseline (speedup 1.0000x reference)
#include <cuda_runtime.h>
#include <stdint.h>

#define BATCH 32
#define NPTS  16384
#define NROT  24
#define IMS   64
#define NPIX  (IMS * IMS)              // 4096
#define NIMG  (BATCH * NROT)           // 768
#define TOT   (NIMG * NPIX)            // 3,145,728
#define NSLOT 32

// Winner-only scratch: (n+1) of the last-written (max-n) point per pixel.
// 12.6 MB -> fully L2-resident. Zero-initialized at module load; unpack
// re-zeroes every call so graph replays see clean state.
__device__ unsigned g_win[TOT];
// Pixel-0 spread slots: all writes targeting pixel (0,0) of image (b,r)
// (masked/out-of-range points AND genuine (0,0) hits) land here, spread
// over 32 slots to avoid same-address LTS serialization.
__device__ unsigned g_hot[NIMG * NSLOT];

__global__ __launch_bounds__(256) void scatter_kernel(
    const float* __restrict__ xyz, const float* __restrict__ rot)
{
    __shared__ float4 srot[NROT];   // (m00, m02, m20, m22) = (c, -s, s, c)
    int tid = threadIdx.x;
    if (tid < NROT) {
        const float* m = rot + tid * 9;
        srot[tid] = make_float4(m[0], m[2], m[6], m[8]);
    }
    __syncthreads();

    int p = blockIdx.x * 256 + tid;     // point index; block is within one batch
    int b = p >> 14;
    int n = p & (NPTS - 1);
    int lane = tid & 31;
    int slot = (p >> 5) & (NSLOT - 1);  // per-warp slot spread

    float x = xyz[p * 3 + 0];
    float y = xyz[p * 3 + 1];
    float z = xyz[p * 3 + 2];

    // Rotation is about y: py is rotation-invariant, computed once.
    int py = (int)rintf((y + 2.0f) * 16.0f);
    bool py_in = (py >= 0) & (py < IMS);
    int py_off = py * IMS;

    unsigned key = (unsigned)(n + 1);
    unsigned* wbase = g_win + (size_t)b * NROT * NPIX;
    unsigned* hbase = g_hot + b * NROT * NSLOT;

#pragma unroll
    for (int r = 0; r < NROT; r++) {
        float4 m = srot[r];
        float xr = fmaf(m.y, z, m.x * x);       // matches XLA fma chain; 0*y exact
        int px = (int)rintf((xr + 2.0f) * 16.0f);
        bool in = py_in & (px >= 0) & (px < IMS);
        int pix = in ? (py_off + px) : 0;       // masked -> pixel 0
        bool to0 = (pix == 0);

        // Warp-reduce max key among lanes targeting pixel 0 (u32 shfl, cheap).
        unsigned rk = to0 ? key : 0u;
        rk = max(rk, __shfl_xor_sync(0xffffffffu, rk, 16));
        rk = max(rk, __shfl_xor_sync(0xffffffffu, rk, 8));
        rk = max(rk, __shfl_xor_sync(0xffffffffu, rk, 4));
        rk = max(rk, __shfl_xor_sync(0xffffffffu, rk, 2));
        rk = max(rk, __shfl_xor_sync(0xffffffffu, rk, 1));

        if (!to0) atomicMax(wbase + r * NPIX + pix, key);
        if (lane == 0 && rk) atomicMax(hbase + r * NSLOT + slot, rk);
    }
}

__global__ __launch_bounds__(256) void unpack_kernel(
    const float* __restrict__ xyz, const float* __restrict__ rot,
    float* __restrict__ out)
{
    int i = blockIdx.x * 256 + threadIdx.x;   // output pixel, [B,R,64,64] layout
    int img = i >> 12;
    int pix = i & (NPIX - 1);

    unsigned w = g_win[i];
    g_win[i] = 0u;                            // reset for next replay

    if (pix == 0) {
        unsigned* h = g_hot + img * NSLOT;
#pragma unroll
        for (int s = 0; s < NSLOT; s++) { w = max(w, h[s]); h[s] = 0u; }
    }

    float val = 0.0f;
    if (w) {
        int b = img / NROT;
        int r = img - b * NROT;
        int n = (int)w - 1;
        const float* pt = xyz + ((size_t)b * NPTS + n) * 3;
        float x = pt[0];
        float z = pt[2];
        float m20 = rot[r * 9 + 6];
        float m22 = rot[r * 9 + 8];
        // Identical FP sequence to the original in-scatter computation.
        val = __fdiv_rn(fmaf(m22, z, m20 * x), 10.0f);
    }
    out[i] = val;
}

extern "C" void kernel_launch(void* const* d_in, const int* in_sizes, int n_in,
                              void* d_out, int out_size)
{
    const float* xyz = (const float*)d_in[0];   // [32, 16384, 3] f32
    const float* rot = (const float*)d_in[1];   // [24, 3, 3] f32
    float* out = (float*)d_out;                 // [32, 24, 64, 64] f32

    scatter_kernel<<<(BATCH * NPTS) / 256, 256>>>(xyz, rot);
    unpack_kernel<<<TOT / 256, 256>>>(xyz, rot, out);
}

// round 7
// speedup vs baseline: 1.3260x; 1.3260x over previous
#include <cuda_runtime.h>
#include <stdint.h>

#define BATCH 32
#define NPTS  16384
#define NROT  24
#define IMS   64
#define NPIX  (IMS * IMS)              // 4096
#define NIMG  (BATCH * NROT)           // 768
#define TOT   (NIMG * NPIX)            // 3,145,728
#define NBUCK 65                       // 64 py rows + 1 OOR bucket
#define CAP   1024                     // bucket capacity (max real ~530, 6-sigma margin)

// key = p+1 (p = b*16384+n). Within one image all contributions share b, so
// max key <=> max n = last-write-wins of the reference scatter.
__device__ unsigned g_win[TOT];                    // 12.6 MB, zero-init at load
__device__ unsigned g_cnt[BATCH * NBUCK];          // bucket counters
__device__ unsigned g_buck[BATCH * NBUCK * CAP];   // point ids (8.5 MB)

// ---------------------------------------------------------------- kernel 1
// Bucket points by (batch, py). py is rotation-invariant (rotation about y).
// 64 blocks per batch exactly, so b is block-uniform.
__global__ __launch_bounds__(256) void bucket_kernel(const float* __restrict__ xyz)
{
    __shared__ unsigned scnt[NBUCK];
    __shared__ unsigned sbase[NBUCK];
    int tid = threadIdx.x;
    if (tid < NBUCK) scnt[tid] = 0u;
    __syncthreads();

    int p = blockIdx.x * 256 + tid;
    int b = p >> 14;
    float y = xyz[p * 3 + 1];
    int py = (int)rintf((y + 2.0f) * 16.0f);
    int bk = ((unsigned)py < IMS) ? py : 64;          // OOR py -> bucket 64
    unsigned rank = atomicAdd(&scnt[bk], 1u);
    __syncthreads();

    if (tid < NBUCK && scnt[tid])
        sbase[tid] = atomicAdd(&g_cnt[b * NBUCK + tid], scnt[tid]);
    __syncthreads();

    g_buck[(b * NBUCK + bk) * CAP + sbase[bk] + rank] = (unsigned)p;
}

// ---------------------------------------------------------------- kernel 2
// One CTA per (batch, bucket). All lanes share py -> each rotation's 32
// atomics land in one 256B row (coalesced wavefronts).
__global__ __launch_bounds__(256) void scatter_kernel(
    const float* __restrict__ xyz, const float* __restrict__ rot)
{
    __shared__ float2 srot[NROT];   // (m00, m02) = (c, -s); px needs only these
    int tid = threadIdx.x;
    if (tid < NROT) {
        const float* m = rot + tid * 9;
        srot[tid] = make_float2(m[0], m[2]);
    }
    __syncthreads();

    int bk = blockIdx.x % NBUCK;
    int b  = blockIdx.x / NBUCK;
    unsigned cnt = g_cnt[b * NBUCK + bk];
    const unsigned* buck = g_buck + (b * NBUCK + bk) * CAP;
    unsigned* wbase = g_win + (size_t)b * NROT * NPIX;

    if (bk == 64) {
        // py-OOR points are masked for ALL rotations -> pixel 0 of every image
        // of this batch. Only the max key survives; reduce then 24 atomics/warp.
        unsigned best = 0u;
        for (unsigned i = tid; i < cnt; i += 256) best = max(best, buck[i] + 1u);
        best = __reduce_max_sync(0xffffffffu, best);
        if ((tid & 31) == 0 && best) {
#pragma unroll
            for (int r = 0; r < NROT; r++) atomicMax(wbase + r * NPIX, best);
        }
        return;
    }

    int rowoff = bk * IMS;
    unsigned cnt_pad = (cnt + 255u) & ~255u;   // uniform trip count
    for (unsigned i = tid; i < cnt_pad; i += 256) {
        bool act = i < cnt;
        unsigned p = act ? buck[i] : 0u;
        unsigned key = p + 1u;
        float x = act ? xyz[p * 3 + 0] : 0.0f;
        float z = act ? xyz[p * 3 + 2] : 0.0f;
#pragma unroll
        for (int r = 0; r < NROT; r++) {
            float2 m = srot[r];
            float xr = fmaf(m.y, z, m.x * x);          // matches XLA fma; 0*y exact
            int px = (int)rintf((xr + 2.0f) * 16.0f);
            bool in = ((unsigned)px < IMS);
            int pix = in ? (rowoff + px) : 0;          // px-OOR -> pixel 0
            if (act) atomicMax(wbase + r * NPIX + pix, key);
        }
    }
}

// ---------------------------------------------------------------- kernel 3
// key -> value: gather (x,z) of the winning point, recompute val with the
// identical FP sequence. Also resets all scratch for the next graph replay.
__global__ __launch_bounds__(256) void unpack_kernel(
    const float* __restrict__ xyz, const float* __restrict__ rot,
    float* __restrict__ out)
{
    int i = blockIdx.x * 256 + threadIdx.x;
    unsigned w = g_win[i];
    g_win[i] = 0u;
    if (i < BATCH * NBUCK) g_cnt[i] = 0u;

    float val = 0.0f;
    if (w) {
        unsigned p = w - 1u;
        int img = i >> 12;
        int r = img % NROT;
        float x = xyz[p * 3 + 0];
        float z = xyz[p * 3 + 2];
        val = __fdiv_rn(fmaf(rot[r * 9 + 8], z, rot[r * 9 + 6] * x), 10.0f);
    }
    out[i] = val;
}

extern "C" void kernel_launch(void* const* d_in, const int* in_sizes, int n_in,
                              void* d_out, int out_size)
{
    const float* xyz = (const float*)d_in[0];   // [32, 16384, 3] f32
    const float* rot = (const float*)d_in[1];   // [24, 3, 3] f32
    float* out = (float*)d_out;                 // [32, 24, 64, 64] f32

    bucket_kernel<<<(BATCH * NPTS) / 256, 256>>>(xyz);
    scatter_kernel<<<BATCH * NBUCK, 256>>>(xyz, rot);
    unpack_kernel<<<TOT / 256, 256>>>(xyz, rot, out);
}